// round 11
// baseline (speedup 1.0000x reference)
#include <cuda_runtime.h>
#include <cuda_fp16.h>
#include <math.h>
#include <stdint.h>

#define BB 32
#define NN 64
#define EE 4096      // NN*NN
#define HID 256
#define NL 9

// ======================= device scratch =======================
__device__ float g_h[2][BB * NN * HID];
__device__ float g_x[2][BB * NN * 3];
__device__ float g_din[BB * EE];
__device__ float g_P[4][BB * NN * HID];   // h@Wa, h@Wb (edge MLP), h@Xa, h@Xb (coord MLP)
__device__ float g_em[BB * NN * HID];
// int8 limbs of W2^T per (branch,layer): Bt[n][k] = W2[k][n] = sB_n*(B1 + B2/256)
__device__ __align__(16) int8_t g_B1[2 * NL * HID * HID];
__device__ __align__(16) int8_t g_B2[2 * NL * HID * HID];
__device__ float g_sB[2 * NL * HID];

__device__ __forceinline__ float siluf(float v) { return v / (1.f + __expf(-v)); }
__device__ __forceinline__ float sigmf_(float v) { return 1.f / (1.f + __expf(-v)); }

__device__ __forceinline__ uint32_t smem_u32(const void* p) {
    uint32_t a;
    asm("{ .reg .u64 t; cvta.to.shared.u64 t, %1; cvt.u32.u64 %0, t; }" : "=r"(a) : "l"(p));
    return a;
}

// int8 tensor-core MMA (sm_80+): D(16x8) s32 += A(16x32) s8 * B(32x8) s8
__device__ __forceinline__ void imma16832(int* c, const uint32_t* a, uint32_t b0, uint32_t b1) {
    asm volatile(
        "mma.sync.aligned.m16n8k32.row.col.s32.s8.s8.s32 "
        "{%0,%1,%2,%3},{%4,%5,%6,%7},{%8,%9},{%0,%1,%2,%3};"
        : "+r"(c[0]), "+r"(c[1]), "+r"(c[2]), "+r"(c[3])
        : "r"(a[0]), "r"(a[1]), "r"(a[2]), "r"(a[3]), "r"(b0), "r"(b1));
}

__device__ __forceinline__ void cpasync16(uint32_t s, const void* g) {
    asm volatile("cp.async.ca.shared.global [%0], [%1], 16;" :: "r"(s), "l"(g));
}
#define CP_COMMIT() asm volatile("cp.async.commit_group;" ::: "memory")
#define CP_WAIT1()  asm volatile("cp.async.wait_group 1;" ::: "memory")
#define CP_WAIT0()  asm volatile("cp.async.wait_group 0;" ::: "memory")

// ======================= init kernels =======================
__global__ void k_init(const float* __restrict__ h_in, const float* __restrict__ t,
                       const float* __restrict__ win_w, const float* __restrict__ win_b,
                       const float* __restrict__ x_in) {
    int row = blockIdx.x;
    int n = threadIdx.x;
    __shared__ float sf[6];
    if (n < 5) sf[n] = h_in[row * 5 + n];
    else if (n == 5) sf[5] = t[row];
    __syncthreads();
    float acc = win_b[n];
#pragma unroll
    for (int k = 0; k < 6; k++) acc = fmaf(sf[k], win_w[k * HID + n], acc);
    g_h[0][row * HID + n] = acc;
    if (n < 3) g_x[0][row * 3 + n] = x_in[row * 3 + n];
}

__global__ void k_din(const float* __restrict__ x_in, const float* __restrict__ edge_mask) {
    int ge = blockIdx.x * blockDim.x + threadIdx.x;
    int b = ge >> 12;
    int e = ge & 4095;
    int i = e >> 6, j = e & 63;
    float s = 0.f;
#pragma unroll
    for (int k = 0; k < 3; k++) {
        float d = x_in[(b * NN + i) * 3 + k] - x_in[(b * NN + j) * 3 + k];
        s = fmaf(d, d, s);
    }
    g_din[ge] = sqrtf(fmaxf(s, 1e-12f)) * edge_mask[ge];
}

// transpose + int8-split W2 -> Bt[n][k] limbs with per-n scale
__global__ void k_wsplit(const float* __restrict__ we_w2, const float* __restrict__ wx_w2) {
    int l = blockIdx.x, br = blockIdx.y, n = threadIdx.x;   // 256 threads
    const float* W = (br ? wx_w2 : we_w2) + (size_t)l * HID * HID;
    size_t base = (size_t)(br * NL + l) * HID * HID;
    float mx = 0.f;
    for (int k = 0; k < HID; k++) mx = fmaxf(mx, fabsf(W[k * HID + n]));
    mx = fmaxf(mx, 1e-30f);
    float qs = 126.f / mx;
    g_sB[(br * NL + l) * HID + n] = mx * (1.f / 126.f);
    for (int k = 0; k < HID; k += 4) {
        uint32_t p1 = 0, p2 = 0;
#pragma unroll
        for (int q = 0; q < 4; q++) {
            float f = W[(k + q) * HID + n] * qs;
            int q1 = __float2int_rn(f);
            q1 = max(-127, min(127, q1));
            int q2 = __float2int_rn((f - (float)q1) * 256.f);
            q2 = max(-128, min(127, q2));
            p1 |= (uint32_t)(uint8_t)(int8_t)q1 << (q * 8);
            p2 |= (uint32_t)(uint8_t)(int8_t)q2 << (q * 8);
        }
        *(uint32_t*)(g_B1 + base + (size_t)n * HID + k) = p1;
        *(uint32_t*)(g_B2 + base + (size_t)n * HID + k) = p2;
    }
}

// ======================= per-layer node projections =======================
__global__ void k_proj(int l, int cur,
                       const float* __restrict__ we_w1, const float* __restrict__ wx_w1) {
    int r0 = blockIdx.x * 16;
    int mat = blockIdx.y;
    const float* W;
    if (mat == 0)      W = we_w1 + (size_t)l * 514 * HID;
    else if (mat == 1) W = we_w1 + (size_t)l * 514 * HID + HID * HID;
    else if (mat == 2) W = wx_w1 + (size_t)l * 514 * HID;
    else               W = wx_w1 + (size_t)l * 514 * HID + HID * HID;
    const float* h = g_h[cur];
    __shared__ float sh[16][HID];
    int tid = threadIdx.x;
    for (int idx = tid; idx < 16 * HID; idx += 256)
        sh[idx >> 8][idx & 255] = h[(r0 + (idx >> 8)) * HID + (idx & 255)];
    __syncthreads();
    float acc[16];
#pragma unroll
    for (int r = 0; r < 16; r++) acc[r] = 0.f;
#pragma unroll 8
    for (int k = 0; k < HID; k++) {
        float w = W[k * HID + tid];
#pragma unroll
        for (int r = 0; r < 16; r++) acc[r] = fmaf(sh[r][k], w, acc[r]);
    }
    float* P = g_P[mat];
#pragma unroll
    for (int r = 0; r < 16; r++) P[(r0 + r) * HID + tid] = acc[r];
}

// ======================= fused edge kernel (512 threads, int8 3-limb) =======================
// SMEM byte layout:
#define OFF_SPI   0        // 512 f32
#define OFF_SW0   2048     // 256 f32 (W1 row 512: d^2)
#define OFF_SW1   3072     // 256 f32 (W1 row 513: d_in)
#define OFF_SB1   4096
#define OFF_SB2   5120
#define OFF_SW3   6144
#define OFF_SBS   7168     // 256 f32 per-n B scales
#define OFF_SD2   8192     // 128 f32
#define OFF_SDIN  8704
#define OFF_SMASK 9216
#define OFF_SDV   9728
#define OFF_SDIFF 10240    // 384 f32
#define OFF_SSA   11776    // 64 f32 per-row A scales
#define OFF_SA    12032    // 64 f32 gate values
#define T_A1   12288       // 64 rows x 272B int8 limb1
#define T_A2   29696       // 64 rows x 272B int8 limb2
#define T_B1B0 47104       // 256 rows x 48B
#define T_B2B0 59392
#define T_B1B1 71680
#define T_B2B1 83968
#define T_MS   96256       // union: L fp32 build buffer / epilogue Ms, 64 x 260 f32
#define EG_SMEM 162816

__global__ void __launch_bounds__(512) k_egemm(int l, int cur,
        const float* __restrict__ we_w1, const float* __restrict__ we_b1,
        const float* __restrict__ we_b2,
        const float* __restrict__ attn_w, const float* __restrict__ attn_b,
        const float* __restrict__ wx_w1, const float* __restrict__ wx_b1,
        const float* __restrict__ wx_b2, const float* __restrict__ wx_w3,
        const float* __restrict__ edge_mask, const float* __restrict__ node_mask) {
    extern __shared__ char sm[];
    uint32_t sbase = smem_u32(sm);
    float* sPi2  = (float*)(sm + OFF_SPI);
    float* sw0   = (float*)(sm + OFF_SW0);
    float* sw1   = (float*)(sm + OFF_SW1);
    float* sb1   = (float*)(sm + OFF_SB1);
    float* sb2   = (float*)(sm + OFF_SB2);
    float* sw3   = (float*)(sm + OFF_SW3);
    float* sbS   = (float*)(sm + OFF_SBS);
    float* sd2   = (float*)(sm + OFF_SD2);
    float* sdin  = (float*)(sm + OFF_SDIN);
    float* smask = (float*)(sm + OFF_SMASK);
    float* sdv   = (float*)(sm + OFF_SDV);
    float* sdiff = (float*)(sm + OFF_SDIFF);
    float* ssA   = (float*)(sm + OFF_SSA);
    float* sa    = (float*)(sm + OFF_SA);
    float* Ms    = (float*)(sm + T_MS);

    int tile = blockIdx.x;        // 0..1023
    int br = blockIdx.y;
    int tid = threadIdx.x;
    int wid = tid >> 5, lane = tid & 31;
    int lg = lane >> 2, tig = lane & 3;
    int b = tile >> 5;
    int bi0 = tile * 2;

    const float* W1 = (br ? wx_w1 : we_w1) + (size_t)l * 514 * HID;
    const float* b1 = (br ? wx_b1 : we_b1) + l * HID;
    const float* b2 = (br ? wx_b2 : we_b2) + l * HID;
    const float* Pi = g_P[br * 2];
    const float* Pj = g_P[br * 2 + 1];
    const float* x  = g_x[cur];
    const int8_t* B1g = g_B1 + (size_t)(br * NL + l) * HID * HID;
    const int8_t* B2g = g_B2 + (size_t)(br * NL + l) * HID * HID;

    // ---- prologue ----
    if (tid < 256) {
        sPi2[tid]       = Pi[(size_t)bi0 * HID + tid];
        sPi2[256 + tid] = Pi[(size_t)(bi0 + 1) * HID + tid];
        sw0[tid] = W1[512 * HID + tid];
        sw1[tid] = W1[513 * HID + tid];
        sb1[tid] = b1[tid];
        sb2[tid] = b2[tid];
        sw3[tid] = br ? wx_w3[l * HID + tid] : attn_w[l * HID + tid];
        sbS[tid] = g_sB[(br * NL + l) * HID + tid];
    }
    if (tid < 128) {
        int gsel = tid >> 6, j = tid & 63;
        int i = (bi0 & 63) + gsel;
        float m = edge_mask[b * EE + i * NN + j];
        float ss = 0.f;
#pragma unroll
        for (int k = 0; k < 3; k++) {
            float dk = (x[(b * NN + i) * 3 + k] - x[(b * NN + j) * 3 + k]) * m;
            sdiff[tid * 3 + k] = dk;
            ss = fmaf(dk, dk, ss);
        }
        ss = fmaxf(ss, 1e-12f);
        sd2[tid] = ss;
        sdv[tid] = sqrtf(ss);
        sdin[tid] = g_din[b * EE + i * NN + j];
        smask[tid] = m;
    }
    __syncthreads();

    int wm = wid & 1, wn = wid >> 1;   // 32-row band within 64-row group, 32-col band

    auto prefetchB = [&](int kc, int bufsel) {
        uint32_t d1 = sbase + (bufsel ? T_B1B1 : T_B1B0);
        uint32_t d2_ = sbase + (bufsel ? T_B2B1 : T_B2B0);
        int n = tid >> 1, q = tid & 1;
        cpasync16(d1 + n * 48 + q * 16, B1g + (size_t)n * HID + kc * 32 + q * 16);
        cpasync16(d2_ + n * 48 + q * 16, B2g + (size_t)n * HID + kc * 32 + q * 16);
        CP_COMMIT();
    };

    for (int g = 0; g < 2; g++) {
        // ---- build L (fp32, in Ms region) + row max ----
        int j = tid >> 3, qq = tid & 7;
        int e = g * 64 + j;
        float d2v = sd2[e], dinv = sdin[e], mv = smask[e];
        const float* pjrow = Pj + (size_t)(b * NN + j) * HID;
        const float* pig = sPi2 + g * 256;
        float* Lrow = Ms + j * 260;
        float mx = 0.f;
#pragma unroll
        for (int s = 0; s < 8; s++) {
            int c = qq * 4 + s * 32;
            float4 pj = *(const float4*)(pjrow + c);
            float4 v;
            float pre;
            pre = pig[c + 0] + pj.x; pre = fmaf(d2v, sw0[c + 0], pre); pre = fmaf(dinv, sw1[c + 0], pre);
            v.x = siluf(fmaf(mv, pre, sb1[c + 0]));
            pre = pig[c + 1] + pj.y; pre = fmaf(d2v, sw0[c + 1], pre); pre = fmaf(dinv, sw1[c + 1], pre);
            v.y = siluf(fmaf(mv, pre, sb1[c + 1]));
            pre = pig[c + 2] + pj.z; pre = fmaf(d2v, sw0[c + 2], pre); pre = fmaf(dinv, sw1[c + 2], pre);
            v.z = siluf(fmaf(mv, pre, sb1[c + 2]));
            pre = pig[c + 3] + pj.w; pre = fmaf(d2v, sw0[c + 3], pre); pre = fmaf(dinv, sw1[c + 3], pre);
            v.w = siluf(fmaf(mv, pre, sb1[c + 3]));
            *(float4*)(Lrow + c) = v;
            mx = fmaxf(mx, fmaxf(fmaxf(fabsf(v.x), fabsf(v.y)), fmaxf(fabsf(v.z), fabsf(v.w))));
        }
        mx = fmaxf(mx, __shfl_xor_sync(0xffffffffu, mx, 1));
        mx = fmaxf(mx, __shfl_xor_sync(0xffffffffu, mx, 2));
        mx = fmaxf(mx, __shfl_xor_sync(0xffffffffu, mx, 4));
        mx = fmaxf(mx, 1e-20f);
        float qs = 126.f / mx;
        if (qq == 0) ssA[j] = mx * (1.f / 126.f);
        // ---- quantize to int8 limbs ----
#pragma unroll
        for (int s = 0; s < 8; s++) {
            int c = qq * 4 + s * 32;
            float4 v = *(const float4*)(Lrow + c);
            uint32_t p1 = 0, p2 = 0;
            float vv[4] = {v.x, v.y, v.z, v.w};
#pragma unroll
            for (int q = 0; q < 4; q++) {
                float f = vv[q] * qs;
                int q1 = __float2int_rn(f);
                q1 = max(-127, min(127, q1));
                int q2 = __float2int_rn((f - (float)q1) * 256.f);
                q2 = max(-128, min(127, q2));
                p1 |= (uint32_t)(uint8_t)(int8_t)q1 << (q * 8);
                p2 |= (uint32_t)(uint8_t)(int8_t)q2 << (q * 8);
            }
            *(uint32_t*)(sm + T_A1 + j * 272 + c) = p1;
            *(uint32_t*)(sm + T_A2 + j * 272 + c) = p2;
        }
        __syncthreads();

        // ---- int8 GEMM: accH = A1B1, accM = A2B1 + A1B2 ----
        int accH[2][4][4], accM[2][4][4];
#pragma unroll
        for (int mt = 0; mt < 2; mt++)
#pragma unroll
            for (int nt = 0; nt < 4; nt++)
#pragma unroll
                for (int r = 0; r < 4; r++) { accH[mt][nt][r] = 0; accM[mt][nt][r] = 0; }

        prefetchB(0, 0);
        for (int kc = 0; kc < 8; kc++) {
            int buf = kc & 1;
            if (kc < 7) { prefetchB(kc + 1, buf ^ 1); CP_WAIT1(); }
            else        { CP_WAIT0(); }
            __syncthreads();
            const char* B1s = sm + (buf ? T_B1B1 : T_B1B0);
            const char* B2s = sm + (buf ? T_B2B1 : T_B2B0);
            uint32_t a1f[2][4], a2f[2][4];
#pragma unroll
            for (int mt = 0; mt < 2; mt++) {
                uint32_t ad = (uint32_t)(wm * 32 + mt * 16 + lg) * 272 + kc * 32 + tig * 4;
                a1f[mt][0] = *(const uint32_t*)(sm + T_A1 + ad);
                a1f[mt][1] = *(const uint32_t*)(sm + T_A1 + ad + 8 * 272);
                a1f[mt][2] = *(const uint32_t*)(sm + T_A1 + ad + 16);
                a1f[mt][3] = *(const uint32_t*)(sm + T_A1 + ad + 8 * 272 + 16);
                a2f[mt][0] = *(const uint32_t*)(sm + T_A2 + ad);
                a2f[mt][1] = *(const uint32_t*)(sm + T_A2 + ad + 8 * 272);
                a2f[mt][2] = *(const uint32_t*)(sm + T_A2 + ad + 16);
                a2f[mt][3] = *(const uint32_t*)(sm + T_A2 + ad + 8 * 272 + 16);
            }
#pragma unroll
            for (int nt = 0; nt < 4; nt++) {
                uint32_t nb = (uint32_t)(wn * 32 + nt * 8 + lg) * 48 + tig * 4;
                uint32_t b10 = *(const uint32_t*)(B1s + nb);
                uint32_t b11 = *(const uint32_t*)(B1s + nb + 16);
                uint32_t b20 = *(const uint32_t*)(B2s + nb);
                uint32_t b21 = *(const uint32_t*)(B2s + nb + 16);
                imma16832(accH[0][nt], a1f[0], b10, b11);
                imma16832(accM[0][nt], a2f[0], b10, b11);
                imma16832(accM[0][nt], a1f[0], b20, b21);
                imma16832(accH[1][nt], a1f[1], b10, b11);
                imma16832(accM[1][nt], a2f[1], b10, b11);
                imma16832(accM[1][nt], a1f[1], b20, b21);
            }
            __syncthreads();
        }

        // ---- epilogue: stage M = silu(sA*sB*(accH + accM/256) + b2) ----
#pragma unroll
        for (int mt = 0; mt < 2; mt++)
#pragma unroll
            for (int nt = 0; nt < 4; nt++)
#pragma unroll
                for (int r = 0; r < 4; r++) {
                    int row = wm * 32 + mt * 16 + lg + (r >> 1) * 8;
                    int col = wn * 32 + nt * 8 + 2 * tig + (r & 1);
                    float v = ssA[row] * sbS[col] *
                              ((float)accH[mt][nt][r] + 0.00390625f * (float)accM[mt][nt][r]);
                    Ms[row * 260 + col] = siluf(v + sb2[col]);
                }
        __syncthreads();
        // per-row dot with sw3 (rotated, conflict-free)
        {
            int j2 = tid >> 3, q2 = tid & 7;
            const float* Mr = &Ms[j2 * 260 + q2 * 32];
            const float* wr = &sw3[q2 * 32];
            float p = 0.f;
#pragma unroll
            for (int n = 0; n < 32; n++) {
                int nn = (n + 4 * q2) & 31;
                p = fmaf(Mr[nn], wr[nn], p);
            }
            p += __shfl_xor_sync(0xffffffffu, p, 1);
            p += __shfl_xor_sync(0xffffffffu, p, 2);
            p += __shfl_xor_sync(0xffffffffu, p, 4);
            if (q2 == 0) sa[j2] = br ? p : sigmf_(p + attn_b[l]);
        }
        __syncthreads();
        int bi = bi0 + g;
        if (br == 0) {
            if (tid < 256) {
                float s = 0.f;
                for (int j2 = 0; j2 < 64; j2++) s = fmaf(sa[j2], Ms[j2 * 260 + tid], s);
                g_em[(size_t)bi * HID + tid] = s;
            }
        } else if (tid < 3) {
            float accx = 0.f;
            for (int j2 = 0; j2 < 64; j2++) {
                int e2 = g * 64 + j2;
                accx = fmaf(sdiff[e2 * 3 + tid] / (sdv[e2] + 1.f), sa[j2], accx);
            }
            g_x[1 - cur][bi * 3 + tid] = (x[bi * 3 + tid] + accx) * node_mask[bi];
        }
        __syncthreads();   // Ms dead before next group's L build
    }
}

// ======================= node MLP =======================
__global__ void k_hupd(int l, int cur,
        const float* __restrict__ wh_w1, const float* __restrict__ wh_b1,
        const float* __restrict__ wh_w2, const float* __restrict__ wh_b2,
        const float* __restrict__ node_mask) {
    int r0 = blockIdx.x * 16;
    int tid = threadIdx.x;
    __shared__ float sin_[16][512];
    __shared__ float shid[16][HID];
    const float* h = g_h[cur];
    for (int idx = tid; idx < 16 * 512; idx += 256) {
        int r = idx >> 9, k = idx & 511;
        sin_[r][k] = (k < HID) ? h[(r0 + r) * HID + k] : g_em[(r0 + r) * HID + (k - HID)];
    }
    __syncthreads();
    const float* W1 = wh_w1 + (size_t)l * 512 * HID;
    const float* W2 = wh_w2 + (size_t)l * HID * HID;
    float b1v = wh_b1[l * HID + tid];
    float acc[16];
#pragma unroll
    for (int r = 0; r < 16; r++) acc[r] = 0.f;
#pragma unroll 4
    for (int k = 0; k < 512; k++) {
        float w = W1[k * HID + tid];
#pragma unroll
        for (int r = 0; r < 16; r++) acc[r] = fmaf(sin_[r][k], w, acc[r]);
    }
#pragma unroll
    for (int r = 0; r < 16; r++) shid[r][tid] = siluf(acc[r] + b1v);
    __syncthreads();
    float b2v = wh_b2[l * HID + tid];
#pragma unroll
    for (int r = 0; r < 16; r++) acc[r] = 0.f;
#pragma unroll 4
    for (int k = 0; k < HID; k++) {
        float w = W2[k * HID + tid];
#pragma unroll
        for (int r = 0; r < 16; r++) acc[r] = fmaf(shid[r][k], w, acc[r]);
    }
    float* ho = g_h[1 - cur];
#pragma unroll
    for (int r = 0; r < 16; r++) {
        int row = r0 + r;
        ho[row * HID + tid] = (h[row * HID + tid] + acc[r] + b2v) * node_mask[row];
    }
}

// ======================= final =======================
__global__ void k_final(const float* __restrict__ x_in, const float* __restrict__ node_mask,
                        const float* __restrict__ wout_w, const float* __restrict__ wout_b,
                        float* __restrict__ out, int fin) {
    int b = blockIdx.x, tid = threadIdx.x;
    __shared__ float sxd[NN][3];
    __shared__ float smean[3];
    const float* x = g_x[fin];
    const float* h = g_h[fin];
    if (tid < NN) {
        float m = node_mask[b * NN + tid];
#pragma unroll
        for (int k = 0; k < 3; k++)
            sxd[tid][k] = (x[(b * NN + tid) * 3 + k] - x_in[(b * NN + tid) * 3 + k]) * m;
    }
    __syncthreads();
    if (tid < 3) {
        float s = 0.f, n = 0.f;
        for (int nd = 0; nd < NN; nd++) { s += sxd[nd][tid]; n += node_mask[b * NN + nd]; }
        smean[tid] = s / n;
    }
    __syncthreads();
    if (tid < NN) {
        float m = node_mask[b * NN + tid];
#pragma unroll
        for (int k = 0; k < 3; k++)
            out[(b * NN + tid) * 8 + k] = (sxd[tid][k] - smean[k]) * m;
    }
    for (int p = tid; p < NN * 5; p += 256) {
        int nd = p / 5, c = p % 5;
        float accv = wout_b[c];
        const float* hr = &h[(b * NN + nd) * HID];
        for (int k = 0; k < HID; k++) accv = fmaf(hr[k], wout_w[k * 6 + c], accv);
        out[(b * NN + nd) * 8 + 3 + c] = accv * node_mask[b * NN + nd];
    }
}

// ======================= host launcher =======================
extern "C" void kernel_launch(void* const* d_in, const int* in_sizes, int n_in,
                              void* d_out, int out_size) {
    const float* x_in      = (const float*)d_in[0];
    const float* h_in      = (const float*)d_in[1];
    const float* t         = (const float*)d_in[2];
    const float* node_mask = (const float*)d_in[3];
    const float* edge_mask = (const float*)d_in[4];
    const float* win_w  = (const float*)d_in[6];
    const float* win_b  = (const float*)d_in[7];
    const float* wout_w = (const float*)d_in[8];
    const float* wout_b = (const float*)d_in[9];
    const float* we_w1  = (const float*)d_in[10];
    const float* we_b1  = (const float*)d_in[11];
    const float* we_w2  = (const float*)d_in[12];
    const float* we_b2  = (const float*)d_in[13];
    const float* attn_w = (const float*)d_in[14];
    const float* attn_b = (const float*)d_in[15];
    const float* wh_w1  = (const float*)d_in[16];
    const float* wh_b1  = (const float*)d_in[17];
    const float* wh_w2  = (const float*)d_in[18];
    const float* wh_b2  = (const float*)d_in[19];
    const float* wx_w1  = (const float*)d_in[20];
    const float* wx_b1  = (const float*)d_in[21];
    const float* wx_w2  = (const float*)d_in[22];
    const float* wx_b2  = (const float*)d_in[23];
    const float* wx_w3  = (const float*)d_in[24];
    float* out = (float*)d_out;

    cudaFuncSetAttribute(k_egemm, cudaFuncAttributeMaxDynamicSharedMemorySize, EG_SMEM);

    k_init<<<BB * NN, 256>>>(h_in, t, win_w, win_b, x_in);
    k_din<<<BB * EE / 256, 256>>>(x_in, edge_mask);
    k_wsplit<<<dim3(NL, 2), 256>>>(we_w2, wx_w2);

    for (int l = 0; l < NL; l++) {
        int cur = l & 1;
        k_proj<<<dim3(BB * NN / 16, 4), 256>>>(l, cur, we_w1, wx_w1);
        k_egemm<<<dim3(BB * EE / 128, 2), 512, EG_SMEM>>>(l, cur,
            we_w1, we_b1, we_b2, attn_w, attn_b,
            wx_w1, wx_b1, wx_b2, wx_w3, edge_mask, node_mask);
        k_hupd<<<BB * NN / 16, 256>>>(l, cur, wh_w1, wh_b1, wh_w2, wh_b2, node_mask);
    }
    k_final<<<BB, 256>>>(x_in, node_mask, wout_w, wout_b, out, 1);
}

// round 15
// speedup vs baseline: 1.4620x; 1.4620x over previous
#include <cuda_runtime.h>
#include <cuda_fp16.h>
#include <math.h>
#include <stdint.h>

#define BB 32
#define NN 64
#define EE 4096      // NN*NN
#define HID 256
#define NL 9

// ======================= device scratch =======================
__device__ float g_h[2][BB * NN * HID];
__device__ float g_x[2][BB * NN * 3];
__device__ float g_din[BB * EE];
__device__ float g_P[4][BB * NN * HID];   // h@Wa, h@Wb (edge MLP), h@Xa, h@Xb (coord MLP)
__device__ float g_em[BB * NN * HID];
// transposed fp16-split W2 per (branch, layer): Bt[n][k] = W2[k][n]
__device__ __half g_Bhi[2 * NL * HID * HID];
__device__ __half g_Blo[2 * NL * HID * HID];

__device__ __forceinline__ float siluf(float v) { return v / (1.f + __expf(-v)); }
__device__ __forceinline__ float sigmf_(float v) { return 1.f / (1.f + __expf(-v)); }

__device__ __forceinline__ uint32_t smem_u32(const void* p) {
    uint32_t a;
    asm("{ .reg .u64 t; cvta.to.shared.u64 t, %1; cvt.u32.u64 %0, t; }" : "=r"(a) : "l"(p));
    return a;
}

// portable fp16 tensor-core MMA (sm_80+): D(16x8) += A(16x16) * B(16x8), fp32 accum
__device__ __forceinline__ void mma16816(float* c, const uint32_t* a, uint32_t b0, uint32_t b1) {
    asm volatile(
        "mma.sync.aligned.m16n8k16.row.col.f32.f16.f16.f32 "
        "{%0,%1,%2,%3},{%4,%5,%6,%7},{%8,%9},{%0,%1,%2,%3};"
        : "+f"(c[0]), "+f"(c[1]), "+f"(c[2]), "+f"(c[3])
        : "r"(a[0]), "r"(a[1]), "r"(a[2]), "r"(a[3]), "r"(b0), "r"(b1));
}

__device__ __forceinline__ void cpasync16(uint32_t s, const void* g) {
    asm volatile("cp.async.ca.shared.global [%0], [%1], 16;" :: "r"(s), "l"(g));
}
#define CP_COMMIT() asm volatile("cp.async.commit_group;" ::: "memory")
#define CP_WAIT1()  asm volatile("cp.async.wait_group 1;" ::: "memory")
#define CP_WAIT0()  asm volatile("cp.async.wait_group 0;" ::: "memory")

// ======================= init kernels =======================
__global__ void k_init(const float* __restrict__ h_in, const float* __restrict__ t,
                       const float* __restrict__ win_w, const float* __restrict__ win_b,
                       const float* __restrict__ x_in) {
    int row = blockIdx.x;
    int n = threadIdx.x;
    __shared__ float sf[6];
    if (n < 5) sf[n] = h_in[row * 5 + n];
    else if (n == 5) sf[5] = t[row];
    __syncthreads();
    float acc = win_b[n];
#pragma unroll
    for (int k = 0; k < 6; k++) acc = fmaf(sf[k], win_w[k * HID + n], acc);
    g_h[0][row * HID + n] = acc;
    if (n < 3) g_x[0][row * 3 + n] = x_in[row * 3 + n];
}

__global__ void k_din(const float* __restrict__ x_in, const float* __restrict__ edge_mask) {
    int ge = blockIdx.x * blockDim.x + threadIdx.x;
    int b = ge >> 12;
    int e = ge & 4095;
    int i = e >> 6, j = e & 63;
    float s = 0.f;
#pragma unroll
    for (int k = 0; k < 3; k++) {
        float d = x_in[(b * NN + i) * 3 + k] - x_in[(b * NN + j) * 3 + k];
        s = fmaf(d, d, s);
    }
    g_din[ge] = sqrtf(fmaxf(s, 1e-12f)) * edge_mask[ge];
}

// transpose + fp16-split W2 -> Bt[n][k] hi/lo
__global__ void k_wsplit(const float* __restrict__ we_w2, const float* __restrict__ wx_w2) {
    int l = blockIdx.x, br = blockIdx.y, tid = threadIdx.x;
    const float* W = (br ? wx_w2 : we_w2) + (size_t)l * HID * HID;
    __half* Bh = g_Bhi + (size_t)(br * NL + l) * HID * HID;
    __half* Bl = g_Blo + (size_t)(br * NL + l) * HID * HID;
    for (int idx = tid; idx < HID * HID; idx += 256) {
        int k = idx >> 8, n = idx & 255;
        float w = W[idx];
        __half h = __float2half_rn(w);
        Bh[n * HID + k] = h;
        Bl[n * HID + k] = __float2half_rn(w - __half2float(h));
    }
}

// ======================= per-layer node projections =======================
__global__ void k_proj(int l, int cur,
                       const float* __restrict__ we_w1, const float* __restrict__ wx_w1) {
    int r0 = blockIdx.x * 16;
    int mat = blockIdx.y;
    const float* W;
    if (mat == 0)      W = we_w1 + (size_t)l * 514 * HID;
    else if (mat == 1) W = we_w1 + (size_t)l * 514 * HID + HID * HID;
    else if (mat == 2) W = wx_w1 + (size_t)l * 514 * HID;
    else               W = wx_w1 + (size_t)l * 514 * HID + HID * HID;
    const float* h = g_h[cur];
    __shared__ float sh[16][HID];
    int tid = threadIdx.x;
    for (int idx = tid; idx < 16 * HID; idx += 256)
        sh[idx >> 8][idx & 255] = h[(r0 + (idx >> 8)) * HID + (idx & 255)];
    __syncthreads();
    float acc[16];
#pragma unroll
    for (int r = 0; r < 16; r++) acc[r] = 0.f;
#pragma unroll 8
    for (int k = 0; k < HID; k++) {
        float w = W[k * HID + tid];
#pragma unroll
        for (int r = 0; r < 16; r++) acc[r] = fmaf(sh[r][k], w, acc[r]);
    }
    float* P = g_P[mat];
#pragma unroll
    for (int r = 0; r < 16; r++) P[(r0 + r) * HID + tid] = acc[r];
}

// ======================= fused edge kernel (512 threads, fp16 2-pass br0 / 3-pass br1) =======================
// SMEM byte layout (dynamic):
#define OFF_SPI   0        // 2*256 f32
#define OFF_SW0   2048     // 256 f32 (W1 row 512: d^2)
#define OFF_SW1   3072     // 256 f32 (W1 row 513: d_in)
#define OFF_SB1   4096
#define OFF_SB2   5120
#define OFF_SW3   6144
#define OFF_SD2   7168     // 128 f32
#define OFF_SDIN  7680
#define OFF_SMASK 8192
#define OFF_SDV   8704
#define OFF_SA    9216     // 64 f32
#define OFF_SDIFF 9472     // 384 f32
#define OFF_TILE  11264
#define T_AH  (OFF_TILE)             // 128 rows x 80B
#define T_AL  (OFF_TILE + 10240)
#define T_BH0 (OFF_TILE + 20480)     // 256 rows x 80B, double-buffered
#define T_BH1 (OFF_TILE + 40960)
#define T_BL0 (OFF_TILE + 61440)
#define T_BL1 (OFF_TILE + 81920)
#define T_P0  (OFF_TILE + 102400)    // 64 rows x 144B (36 f32 pitch)
#define T_P1  (OFF_TILE + 111616)
#define T_MS  (OFF_TILE)             // epilogue union: 64 x 260 f32
#define EG_SMEM (OFF_TILE + 120832)  // 132096

__global__ void __launch_bounds__(512) k_egemm(int l, int cur,
        const float* __restrict__ we_w1, const float* __restrict__ we_b1,
        const float* __restrict__ we_b2,
        const float* __restrict__ attn_w, const float* __restrict__ attn_b,
        const float* __restrict__ wx_w1, const float* __restrict__ wx_b1,
        const float* __restrict__ wx_b2, const float* __restrict__ wx_w3,
        const float* __restrict__ edge_mask, const float* __restrict__ node_mask) {
    extern __shared__ char sm[];
    uint32_t sbase = smem_u32(sm);
    float* sPi2  = (float*)(sm + OFF_SPI);
    float* sw0   = (float*)(sm + OFF_SW0);
    float* sw1   = (float*)(sm + OFF_SW1);
    float* sb1   = (float*)(sm + OFF_SB1);
    float* sb2   = (float*)(sm + OFF_SB2);
    float* sw3   = (float*)(sm + OFF_SW3);
    float* sd2   = (float*)(sm + OFF_SD2);
    float* sdin  = (float*)(sm + OFF_SDIN);
    float* smask = (float*)(sm + OFF_SMASK);
    float* sdv   = (float*)(sm + OFF_SDV);
    float* sa    = (float*)(sm + OFF_SA);
    float* sdiff = (float*)(sm + OFF_SDIFF);

    int tile = blockIdx.x;        // 0..1023
    int br = blockIdx.y;
    int tid = threadIdx.x;
    int wid = tid >> 5, lane = tid & 31;
    int g = lane >> 2, tig = lane & 3;
    int b = tile >> 5;
    int bi0 = tile * 2;

    const float* W1 = (br ? wx_w1 : we_w1) + (size_t)l * 514 * HID;
    const float* b1 = (br ? wx_b1 : we_b1) + l * HID;
    const float* b2 = (br ? wx_b2 : we_b2) + l * HID;
    const float* Pi = g_P[br * 2];
    const float* Pj = g_P[br * 2 + 1];
    const float* x  = g_x[cur];
    const __half* Bhg = g_Bhi + (size_t)(br * NL + l) * HID * HID;
    const __half* Blg = g_Blo + (size_t)(br * NL + l) * HID * HID;

    // ---- prologue ----
    if (tid < 256) {
        sPi2[tid]       = Pi[(size_t)bi0 * HID + tid];
        sPi2[256 + tid] = Pi[(size_t)(bi0 + 1) * HID + tid];
        sw0[tid] = W1[512 * HID + tid];
        sw1[tid] = W1[513 * HID + tid];
        sb1[tid] = b1[tid];
        sb2[tid] = b2[tid];
        sw3[tid] = br ? wx_w3[l * HID + tid] : attn_w[l * HID + tid];
    }
    if (tid < 128) {
        int gsel = tid >> 6, j = tid & 63;
        int i = (bi0 & 63) + gsel;
        float m = edge_mask[b * EE + i * NN + j];
        float ss = 0.f;
#pragma unroll
        for (int k = 0; k < 3; k++) {
            float dk = (x[(b * NN + i) * 3 + k] - x[(b * NN + j) * 3 + k]) * m;
            sdiff[tid * 3 + k] = dk;
            ss = fmaf(dk, dk, ss);
        }
        ss = fmaxf(ss, 1e-12f);
        sd2[tid] = ss;
        sdv[tid] = sqrtf(ss);
        sdin[tid] = g_din[b * EE + i * NN + j];
        smask[tid] = m;
    }

    float acc[2][8][4];
#pragma unroll
    for (int mt = 0; mt < 2; mt++)
#pragma unroll
        for (int nt = 0; nt < 8; nt++)
#pragma unroll
            for (int r = 0; r < 4; r++) acc[mt][nt][r] = 0.f;

    int wm = wid & 3, wn = wid >> 2;   // 32-row band, 64-col band

    auto prefetch = [&](int kc, int bufsel) {
        uint32_t bhd = sbase + (bufsel ? T_BH1 : T_BH0);
        uint32_t bld = sbase + (bufsel ? T_BL1 : T_BL0);
        uint32_t pdst = sbase + (bufsel ? T_P1 : T_P0);
        // B hi (and lo only for br==1, the error-critical coordinate branch)
#pragma unroll
        for (int it = 0; it < 2; it++) {
            int idx = it * 512 + tid;
            int n = idx >> 2, q = idx & 3;
            cpasync16(bhd + n * 80 + q * 16, Bhg + (size_t)n * HID + kc * 32 + q * 8);
            if (br == 1)
                cpasync16(bld + n * 80 + q * 16, Blg + (size_t)n * HID + kc * 32 + q * 8);
        }
        // Pj chunk: 64 rows x 128B -> 512 segs, 1/thread
        {
            int j = tid >> 3, q = tid & 7;
            cpasync16(pdst + j * 144 + q * 16, Pj + (size_t)(b * NN + j) * HID + kc * 32 + q * 4);
        }
        CP_COMMIT();
    };

    prefetch(0, 0);

    for (int kc = 0; kc < 8; kc++) {
        int buf = kc & 1;
        if (kc < 7) { prefetch(kc + 1, buf ^ 1); CP_WAIT1(); }
        else        { CP_WAIT0(); }
        __syncthreads();

        // ---- build L tile [128][32] -> fp16 hi/lo ----
        {
            int r = tid >> 2;
            int c0 = (tid & 3) * 8;
            int gsel = r >> 6, j = r & 63;
            float d2v = sd2[r], dinv = sdin[r], mv = smask[r];
            const float* pig = &sPi2[gsel * 256 + kc * 32];
            const float* pjr = (const float*)(sm + (buf ? T_P1 : T_P0)) + j * 36;
#pragma unroll
            for (int cc = 0; cc < 8; cc++) {
                int c = c0 + cc;
                int gcol = kc * 32 + c;
                float pre = pig[c] + pjr[c];
                pre = fmaf(d2v, sw0[gcol], pre);
                pre = fmaf(dinv, sw1[gcol], pre);
                pre = fmaf(mv, pre, sb1[gcol]);
                float v = siluf(pre);
                __half hv = __float2half_rn(v);
                *(__half*)(sm + T_AH + r * 80 + c * 2) = hv;
                *(__half*)(sm + T_AL + r * 80 + c * 2) =
                    __float2half_rn(v - __half2float(hv));
            }
        }
        __syncthreads();

        // ---- HMMA: br1 = Ah*Bh + Al*Bh + Ah*Bl ; br0 = Ah*Bh + Al*Bh ----
        {
            const char* Bhs = sm + (buf ? T_BH1 : T_BH0);
            const char* Bls = sm + (buf ? T_BL1 : T_BL0);
#pragma unroll
            for (int kk = 0; kk < 2; kk++) {
                uint32_t ah[2][4], al[2][4];
#pragma unroll
                for (int mt = 0; mt < 2; mt++) {
                    uint32_t ad = (uint32_t)(wm * 32 + mt * 16 + g) * 80 + kk * 32 + tig * 4;
                    ah[mt][0] = *(const uint32_t*)(sm + T_AH + ad);
                    ah[mt][1] = *(const uint32_t*)(sm + T_AH + ad + 640);
                    ah[mt][2] = *(const uint32_t*)(sm + T_AH + ad + 16);
                    ah[mt][3] = *(const uint32_t*)(sm + T_AH + ad + 656);
                    al[mt][0] = *(const uint32_t*)(sm + T_AL + ad);
                    al[mt][1] = *(const uint32_t*)(sm + T_AL + ad + 640);
                    al[mt][2] = *(const uint32_t*)(sm + T_AL + ad + 16);
                    al[mt][3] = *(const uint32_t*)(sm + T_AL + ad + 656);
                }
#pragma unroll
                for (int nt = 0; nt < 8; nt++) {
                    uint32_t bd = (uint32_t)(wn * 64 + nt * 8 + g) * 80 + kk * 32 + tig * 4;
                    uint32_t bh0 = *(const uint32_t*)(Bhs + bd);
                    uint32_t bh1 = *(const uint32_t*)(Bhs + bd + 16);
                    mma16816(acc[0][nt], ah[0], bh0, bh1);
                    mma16816(acc[0][nt], al[0], bh0, bh1);
                    mma16816(acc[1][nt], ah[1], bh0, bh1);
                    mma16816(acc[1][nt], al[1], bh0, bh1);
                    if (br == 1) {
                        uint32_t bl0 = *(const uint32_t*)(Bls + bd);
                        uint32_t bl1 = *(const uint32_t*)(Bls + bd + 16);
                        mma16816(acc[0][nt], ah[0], bl0, bl1);
                        mma16816(acc[1][nt], ah[1], bl0, bl1);
                    }
                }
            }
        }
        __syncthreads();
    }

    // ---- epilogue: per group, stage M=silu(acc+b2), reduce ----
    float* Ms = (float*)(sm + T_MS);
    for (int gsel = 0; gsel < 2; gsel++) {
        __syncthreads();
        if ((wm >> 1) == gsel) {
#pragma unroll
            for (int mt = 0; mt < 2; mt++)
#pragma unroll
                for (int nt = 0; nt < 8; nt++)
#pragma unroll
                    for (int r = 0; r < 4; r++) {
                        int row = wm * 32 + mt * 16 + g + (r >> 1) * 8;
                        int jr = row - gsel * 64;
                        int col = wn * 64 + nt * 8 + 2 * tig + (r & 1);
                        Ms[jr * 260 + col] = siluf(acc[mt][nt][r] + sb2[col]);
                    }
        }
        __syncthreads();
        // per-row dot with sw3 (rotated, conflict-free)
        {
            int j = tid >> 3, qq = tid & 7;
            const float* Mr = &Ms[j * 260 + qq * 32];
            const float* wr = &sw3[qq * 32];
            float p = 0.f;
#pragma unroll
            for (int n = 0; n < 32; n++) {
                int nn = (n + 4 * qq) & 31;
                p = fmaf(Mr[nn], wr[nn], p);
            }
            p += __shfl_xor_sync(0xffffffffu, p, 1);
            p += __shfl_xor_sync(0xffffffffu, p, 2);
            p += __shfl_xor_sync(0xffffffffu, p, 4);
            if (qq == 0) sa[j] = br ? p : sigmf_(p + attn_b[l]);
        }
        __syncthreads();
        int bi = bi0 + gsel;
        if (br == 0) {
            if (tid < 256) {
                float s = 0.f;
                for (int j2 = 0; j2 < 64; j2++) s = fmaf(sa[j2], Ms[j2 * 260 + tid], s);
                g_em[(size_t)bi * HID + tid] = s;
            }
        } else if (tid < 3) {
            float accx = 0.f;
            for (int j2 = 0; j2 < 64; j2++) {
                int e = gsel * 64 + j2;
                accx = fmaf(sdiff[e * 3 + tid] / (sdv[e] + 1.f), sa[j2], accx);
            }
            g_x[1 - cur][bi * 3 + tid] = (x[bi * 3 + tid] + accx) * node_mask[bi];
        }
    }
}

// ======================= node MLP =======================
__global__ void k_hupd(int l, int cur,
        const float* __restrict__ wh_w1, const float* __restrict__ wh_b1,
        const float* __restrict__ wh_w2, const float* __restrict__ wh_b2,
        const float* __restrict__ node_mask) {
    int r0 = blockIdx.x * 16;
    int tid = threadIdx.x;
    __shared__ float sin_[16][512];
    __shared__ float shid[16][HID];
    const float* h = g_h[cur];
    for (int idx = tid; idx < 16 * 512; idx += 256) {
        int r = idx >> 9, k = idx & 511;
        sin_[r][k] = (k < HID) ? h[(r0 + r) * HID + k] : g_em[(r0 + r) * HID + (k - HID)];
    }
    __syncthreads();
    const float* W1 = wh_w1 + (size_t)l * 512 * HID;
    const float* W2 = wh_w2 + (size_t)l * HID * HID;
    float b1v = wh_b1[l * HID + tid];
    float acc[16];
#pragma unroll
    for (int r = 0; r < 16; r++) acc[r] = 0.f;
#pragma unroll 4
    for (int k = 0; k < 512; k++) {
        float w = W1[k * HID + tid];
#pragma unroll
        for (int r = 0; r < 16; r++) acc[r] = fmaf(sin_[r][k], w, acc[r]);
    }
#pragma unroll
    for (int r = 0; r < 16; r++) shid[r][tid] = siluf(acc[r] + b1v);
    __syncthreads();
    float b2v = wh_b2[l * HID + tid];
#pragma unroll
    for (int r = 0; r < 16; r++) acc[r] = 0.f;
#pragma unroll 4
    for (int k = 0; k < HID; k++) {
        float w = W2[k * HID + tid];
#pragma unroll
        for (int r = 0; r < 16; r++) acc[r] = fmaf(shid[r][k], w, acc[r]);
    }
    float* ho = g_h[1 - cur];
#pragma unroll
    for (int r = 0; r < 16; r++) {
        int row = r0 + r;
        ho[row * HID + tid] = (h[row * HID + tid] + acc[r] + b2v) * node_mask[row];
    }
}

// ======================= final =======================
__global__ void k_final(const float* __restrict__ x_in, const float* __restrict__ node_mask,
                        const float* __restrict__ wout_w, const float* __restrict__ wout_b,
                        float* __restrict__ out, int fin) {
    int b = blockIdx.x, tid = threadIdx.x;
    __shared__ float sxd[NN][3];
    __shared__ float smean[3];
    const float* x = g_x[fin];
    const float* h = g_h[fin];
    if (tid < NN) {
        float m = node_mask[b * NN + tid];
#pragma unroll
        for (int k = 0; k < 3; k++)
            sxd[tid][k] = (x[(b * NN + tid) * 3 + k] - x_in[(b * NN + tid) * 3 + k]) * m;
    }
    __syncthreads();
    if (tid < 3) {
        float s = 0.f, n = 0.f;
        for (int nd = 0; nd < NN; nd++) { s += sxd[nd][tid]; n += node_mask[b * NN + nd]; }
        smean[tid] = s / n;
    }
    __syncthreads();
    if (tid < NN) {
        float m = node_mask[b * NN + tid];
#pragma unroll
        for (int k = 0; k < 3; k++)
            out[(b * NN + tid) * 8 + k] = (sxd[tid][k] - smean[k]) * m;
    }
    for (int p = tid; p < NN * 5; p += 256) {
        int nd = p / 5, c = p % 5;
        float accv = wout_b[c];
        const float* hr = &h[(b * NN + nd) * HID];
        for (int k = 0; k < HID; k++) accv = fmaf(hr[k], wout_w[k * 6 + c], accv);
        out[(b * NN + nd) * 8 + 3 + c] = accv * node_mask[b * NN + nd];
    }
}

// ======================= host launcher =======================
extern "C" void kernel_launch(void* const* d_in, const int* in_sizes, int n_in,
                              void* d_out, int out_size) {
    const float* x_in      = (const float*)d_in[0];
    const float* h_in      = (const float*)d_in[1];
    const float* t         = (const float*)d_in[2];
    const float* node_mask = (const float*)d_in[3];
    const float* edge_mask = (const float*)d_in[4];
    const float* win_w  = (const float*)d_in[6];
    const float* win_b  = (const float*)d_in[7];
    const float* wout_w = (const float*)d_in[8];
    const float* wout_b = (const float*)d_in[9];
    const float* we_w1  = (const float*)d_in[10];
    const float* we_b1  = (const float*)d_in[11];
    const float* we_w2  = (const float*)d_in[12];
    const float* we_b2  = (const float*)d_in[13];
    const float* attn_w = (const float*)d_in[14];
    const float* attn_b = (const float*)d_in[15];
    const float* wh_w1  = (const float*)d_in[16];
    const float* wh_b1  = (const float*)d_in[17];
    const float* wh_w2  = (const float*)d_in[18];
    const float* wh_b2  = (const float*)d_in[19];
    const float* wx_w1  = (const float*)d_in[20];
    const float* wx_b1  = (const float*)d_in[21];
    const float* wx_w2  = (const float*)d_in[22];
    const float* wx_b2  = (const float*)d_in[23];
    const float* wx_w3  = (const float*)d_in[24];
    float* out = (float*)d_out;

    cudaFuncSetAttribute(k_egemm, cudaFuncAttributeMaxDynamicSharedMemorySize, EG_SMEM);

    k_init<<<BB * NN, 256>>>(h_in, t, win_w, win_b, x_in);
    k_din<<<BB * EE / 256, 256>>>(x_in, edge_mask);
    k_wsplit<<<dim3(NL, 2), 256>>>(we_w2, wx_w2);

    for (int l = 0; l < NL; l++) {
        int cur = l & 1;
        k_proj<<<dim3(BB * NN / 16, 4), 256>>>(l, cur, we_w1, wx_w1);
        k_egemm<<<dim3(BB * EE / 128, 2), 512, EG_SMEM>>>(l, cur,
            we_w1, we_b1, we_b2, attn_w, attn_b,
            wx_w1, wx_b1, wx_b2, wx_w3, edge_mask, node_mask);
        k_hupd<<<BB * NN / 16, 256>>>(l, cur, wh_w1, wh_b1, wh_w2, wh_b2, node_mask);
    }
    k_final<<<BB, 256>>>(x_in, node_mask, wout_w, wout_b, out, 1);
}

// round 17
// speedup vs baseline: 1.8230x; 1.2469x over previous
#include <cuda_runtime.h>
#include <cuda_fp16.h>
#include <math.h>
#include <stdint.h>

#define BB 32
#define NN 64
#define EE 4096      // NN*NN
#define HID 256
#define NL 9

// ======================= device scratch =======================
__device__ float g_h[2][BB * NN * HID];
__device__ float g_x[2][BB * NN * 3];
__device__ float g_din[BB * EE];
__device__ float g_P[4][BB * NN * HID];   // h@Wa, h@Wb (edge MLP), h@Xa, h@Xb (coord MLP)
__device__ float g_em[BB * NN * HID];
// transposed fp16-split W2 per (branch, layer): Bt[n][k] = W2[k][n]
__device__ __half g_Bhi[2 * NL * HID * HID];
__device__ __half g_Blo[2 * NL * HID * HID];

// fast silu/sigmoid: explicit approx PTX (ex2.approx + rcp.approx), ~1e-7 rel err
__device__ __forceinline__ float siluf(float v) {
    float e, r;
    asm("ex2.approx.f32 %0, %1;" : "=f"(e) : "f"(v * -1.44269504f));
    asm("rcp.approx.f32 %0, %1;" : "=f"(r) : "f"(e + 1.f));
    return v * r;
}
__device__ __forceinline__ float sigmf_(float v) {
    float e, r;
    asm("ex2.approx.f32 %0, %1;" : "=f"(e) : "f"(v * -1.44269504f));
    asm("rcp.approx.f32 %0, %1;" : "=f"(r) : "f"(e + 1.f));
    return r;
}

__device__ __forceinline__ uint32_t smem_u32(const void* p) {
    uint32_t a;
    asm("{ .reg .u64 t; cvta.to.shared.u64 t, %1; cvt.u32.u64 %0, t; }" : "=r"(a) : "l"(p));
    return a;
}

// portable fp16 tensor-core MMA (sm_80+): D(16x8) += A(16x16) * B(16x8), fp32 accum
__device__ __forceinline__ void mma16816(float* c, const uint32_t* a, uint32_t b0, uint32_t b1) {
    asm volatile(
        "mma.sync.aligned.m16n8k16.row.col.f32.f16.f16.f32 "
        "{%0,%1,%2,%3},{%4,%5,%6,%7},{%8,%9},{%0,%1,%2,%3};"
        : "+f"(c[0]), "+f"(c[1]), "+f"(c[2]), "+f"(c[3])
        : "r"(a[0]), "r"(a[1]), "r"(a[2]), "r"(a[3]), "r"(b0), "r"(b1));
}

__device__ __forceinline__ void cpasync16(uint32_t s, const void* g) {
    asm volatile("cp.async.ca.shared.global [%0], [%1], 16;" :: "r"(s), "l"(g));
}
#define CP_COMMIT() asm volatile("cp.async.commit_group;" ::: "memory")
#define CP_WAIT0()  asm volatile("cp.async.wait_group 0;" ::: "memory")

// ======================= init kernels =======================
__global__ void k_init(const float* __restrict__ h_in, const float* __restrict__ t,
                       const float* __restrict__ win_w, const float* __restrict__ win_b,
                       const float* __restrict__ x_in) {
    int row = blockIdx.x;
    int n = threadIdx.x;
    __shared__ float sf[6];
    if (n < 5) sf[n] = h_in[row * 5 + n];
    else if (n == 5) sf[5] = t[row];
    __syncthreads();
    float acc = win_b[n];
#pragma unroll
    for (int k = 0; k < 6; k++) acc = fmaf(sf[k], win_w[k * HID + n], acc);
    g_h[0][row * HID + n] = acc;
    if (n < 3) g_x[0][row * 3 + n] = x_in[row * 3 + n];
}

__global__ void k_din(const float* __restrict__ x_in, const float* __restrict__ edge_mask) {
    int ge = blockIdx.x * blockDim.x + threadIdx.x;
    int b = ge >> 12;
    int e = ge & 4095;
    int i = e >> 6, j = e & 63;
    float s = 0.f;
#pragma unroll
    for (int k = 0; k < 3; k++) {
        float d = x_in[(b * NN + i) * 3 + k] - x_in[(b * NN + j) * 3 + k];
        s = fmaf(d, d, s);
    }
    g_din[ge] = sqrtf(fmaxf(s, 1e-12f)) * edge_mask[ge];
}

// transpose + fp16-split W2 -> Bt[n][k] hi/lo
__global__ void k_wsplit(const float* __restrict__ we_w2, const float* __restrict__ wx_w2) {
    int l = blockIdx.x, br = blockIdx.y, tid = threadIdx.x;
    const float* W = (br ? wx_w2 : we_w2) + (size_t)l * HID * HID;
    __half* Bh = g_Bhi + (size_t)(br * NL + l) * HID * HID;
    __half* Bl = g_Blo + (size_t)(br * NL + l) * HID * HID;
    for (int idx = tid; idx < HID * HID; idx += 256) {
        int k = idx >> 8, n = idx & 255;
        float w = W[idx];
        __half h = __float2half_rn(w);
        Bh[n * HID + k] = h;
        Bl[n * HID + k] = __float2half_rn(w - __half2float(h));
    }
}

// ======================= per-layer node projections =======================
__global__ void k_proj(int l, int cur,
                       const float* __restrict__ we_w1, const float* __restrict__ wx_w1) {
    int r0 = blockIdx.x * 16;
    int mat = blockIdx.y;
    const float* W;
    if (mat == 0)      W = we_w1 + (size_t)l * 514 * HID;
    else if (mat == 1) W = we_w1 + (size_t)l * 514 * HID + HID * HID;
    else if (mat == 2) W = wx_w1 + (size_t)l * 514 * HID;
    else               W = wx_w1 + (size_t)l * 514 * HID + HID * HID;
    const float* h = g_h[cur];
    __shared__ float sh[16][HID];
    int tid = threadIdx.x;
    for (int idx = tid; idx < 16 * HID; idx += 256)
        sh[idx >> 8][idx & 255] = h[(r0 + (idx >> 8)) * HID + (idx & 255)];
    __syncthreads();
    float acc[16];
#pragma unroll
    for (int r = 0; r < 16; r++) acc[r] = 0.f;
#pragma unroll 8
    for (int k = 0; k < HID; k++) {
        float w = W[k * HID + tid];
#pragma unroll
        for (int r = 0; r < 16; r++) acc[r] = fmaf(sh[r][k], w, acc[r]);
    }
    float* P = g_P[mat];
#pragma unroll
    for (int r = 0; r < 16; r++) P[(r0 + r) * HID + tid] = acc[r];
}

// ======================= fused edge kernel =======================
// 512 threads, fp16 2-pass br0 / 3-pass br1, A double-buffered, build||MMA overlap.
// SMEM byte layout (dynamic):
#define OFF_SPI   0        // 2*256 f32
#define OFF_SW0   2048     // 256 f32 (W1 row 512: d^2)
#define OFF_SW1   3072     // 256 f32 (W1 row 513: d_in)
#define OFF_SB1   4096
#define OFF_SB2   5120
#define OFF_SW3   6144
#define OFF_SD2   7168     // 128 f32
#define OFF_SDIN  7680
#define OFF_SMASK 8192
#define OFF_SDV   8704
#define OFF_SA    9216     // 64 f32
#define OFF_SDIFF 9472     // 384 f32
#define OFF_TILE  11264
#define T_AHx(b) (OFF_TILE + (b) * 20480)            // 128 rows x 80B
#define T_ALx(b) (OFF_TILE + (b) * 20480 + 10240)
#define T_BHx(b) (OFF_TILE + 40960 + (b) * 20480)    // 256 rows x 80B
#define T_BLx(b) (OFF_TILE + 81920 + (b) * 20480)
#define T_Px(b)  (OFF_TILE + 122880 + (b) * 9216)    // 64 rows x 144B (36 f32 pitch)
#define T_MS  (OFF_TILE)                             // epilogue union: 64 x 260 f32
#define EG_SMEM (OFF_TILE + 141312)                  // 152576

__global__ void __launch_bounds__(512) k_egemm(int l, int cur,
        const float* __restrict__ we_w1, const float* __restrict__ we_b1,
        const float* __restrict__ we_b2,
        const float* __restrict__ attn_w, const float* __restrict__ attn_b,
        const float* __restrict__ wx_w1, const float* __restrict__ wx_b1,
        const float* __restrict__ wx_b2, const float* __restrict__ wx_w3,
        const float* __restrict__ edge_mask, const float* __restrict__ node_mask) {
    extern __shared__ char sm[];
    uint32_t sbase = smem_u32(sm);
    float* sPi2  = (float*)(sm + OFF_SPI);
    float* sw0   = (float*)(sm + OFF_SW0);
    float* sw1   = (float*)(sm + OFF_SW1);
    float* sb1   = (float*)(sm + OFF_SB1);
    float* sb2   = (float*)(sm + OFF_SB2);
    float* sw3   = (float*)(sm + OFF_SW3);
    float* sd2   = (float*)(sm + OFF_SD2);
    float* sdin  = (float*)(sm + OFF_SDIN);
    float* smask = (float*)(sm + OFF_SMASK);
    float* sdv   = (float*)(sm + OFF_SDV);
    float* sa    = (float*)(sm + OFF_SA);
    float* sdiff = (float*)(sm + OFF_SDIFF);

    int tile = blockIdx.x;        // 0..1023
    int br = blockIdx.y;
    int tid = threadIdx.x;
    int wid = tid >> 5, lane = tid & 31;
    int g = lane >> 2, tig = lane & 3;
    int b = tile >> 5;
    int bi0 = tile * 2;

    const float* W1 = (br ? wx_w1 : we_w1) + (size_t)l * 514 * HID;
    const float* b1 = (br ? wx_b1 : we_b1) + l * HID;
    const float* b2 = (br ? wx_b2 : we_b2) + l * HID;
    const float* Pi = g_P[br * 2];
    const float* Pj = g_P[br * 2 + 1];
    const float* x  = g_x[cur];
    const __half* Bhg = g_Bhi + (size_t)(br * NL + l) * HID * HID;
    const __half* Blg = g_Blo + (size_t)(br * NL + l) * HID * HID;

    // ---- prologue ----
    if (tid < 256) {
        sPi2[tid]       = Pi[(size_t)bi0 * HID + tid];
        sPi2[256 + tid] = Pi[(size_t)(bi0 + 1) * HID + tid];
        sw0[tid] = W1[512 * HID + tid];
        sw1[tid] = W1[513 * HID + tid];
        sb1[tid] = b1[tid];
        sb2[tid] = b2[tid];
        sw3[tid] = br ? wx_w3[l * HID + tid] : attn_w[l * HID + tid];
    }
    if (tid < 128) {
        int gsel = tid >> 6, j = tid & 63;
        int i = (bi0 & 63) + gsel;
        float m = edge_mask[b * EE + i * NN + j];
        float ss = 0.f;
#pragma unroll
        for (int k = 0; k < 3; k++) {
            float dk = (x[(b * NN + i) * 3 + k] - x[(b * NN + j) * 3 + k]) * m;
            sdiff[tid * 3 + k] = dk;
            ss = fmaf(dk, dk, ss);
        }
        ss = fmaxf(ss, 1e-12f);
        sd2[tid] = ss;
        sdv[tid] = sqrtf(ss);
        sdin[tid] = g_din[b * EE + i * NN + j];
        smask[tid] = m;
    }

    float acc[2][8][4];
#pragma unroll
    for (int mt = 0; mt < 2; mt++)
#pragma unroll
        for (int nt = 0; nt < 8; nt++)
#pragma unroll
            for (int r = 0; r < 4; r++) acc[mt][nt][r] = 0.f;

    int wm = wid & 3, wn = wid >> 2;   // 32-row band, 64-col band

    auto prefetch = [&](int kc, int bufsel) {
        uint32_t bhd = sbase + T_BHx(bufsel);
        uint32_t bld = sbase + T_BLx(bufsel);
        uint32_t pdst = sbase + T_Px(bufsel);
#pragma unroll
        for (int it = 0; it < 2; it++) {
            int idx = it * 512 + tid;
            int n = idx >> 2, q = idx & 3;
            cpasync16(bhd + n * 80 + q * 16, Bhg + (size_t)n * HID + kc * 32 + q * 8);
            if (br == 1)
                cpasync16(bld + n * 80 + q * 16, Blg + (size_t)n * HID + kc * 32 + q * 8);
        }
        {
            int j = tid >> 3, q = tid & 7;
            cpasync16(pdst + j * 144 + q * 16, Pj + (size_t)(b * NN + j) * HID + kc * 32 + q * 4);
        }
        CP_COMMIT();
    };

    // build L tile [128][32] for k-chunk kcb into A buffer ab, reading Pj buffer pb
    auto buildA = [&](int kcb, int ab, int pb) {
        int r = tid >> 2;
        int c0 = (tid & 3) * 8;
        int gsel = r >> 6, j = r & 63;
        float d2v = sd2[r], dinv = sdin[r], mv = smask[r];
        const float* pig = &sPi2[gsel * 256 + kcb * 32];
        const float* pjr = (const float*)(sm + T_Px(pb)) + j * 36;
#pragma unroll
        for (int cc = 0; cc < 8; cc++) {
            int c = c0 + cc;
            int gcol = kcb * 32 + c;
            float pre = pig[c] + pjr[c];
            pre = fmaf(d2v, sw0[gcol], pre);
            pre = fmaf(dinv, sw1[gcol], pre);
            pre = fmaf(mv, pre, sb1[gcol]);
            float v = siluf(pre);
            __half hv = __float2half_rn(v);
            *(__half*)(sm + T_AHx(ab) + r * 80 + c * 2) = hv;
            *(__half*)(sm + T_ALx(ab) + r * 80 + c * 2) =
                __float2half_rn(v - __half2float(hv));
        }
    };

    // one kk half of the HMMA work for buffer buf
    auto mmaBlk = [&](int kk, int buf) {
        const char* Bhs = sm + T_BHx(buf);
        const char* Bls = sm + T_BLx(buf);
        uint32_t ah[2][4], al[2][4];
#pragma unroll
        for (int mt = 0; mt < 2; mt++) {
            uint32_t ad = (uint32_t)(wm * 32 + mt * 16 + g) * 80 + kk * 32 + tig * 4;
            ah[mt][0] = *(const uint32_t*)(sm + T_AHx(buf) + ad);
            ah[mt][1] = *(const uint32_t*)(sm + T_AHx(buf) + ad + 640);
            ah[mt][2] = *(const uint32_t*)(sm + T_AHx(buf) + ad + 16);
            ah[mt][3] = *(const uint32_t*)(sm + T_AHx(buf) + ad + 656);
            al[mt][0] = *(const uint32_t*)(sm + T_ALx(buf) + ad);
            al[mt][1] = *(const uint32_t*)(sm + T_ALx(buf) + ad + 640);
            al[mt][2] = *(const uint32_t*)(sm + T_ALx(buf) + ad + 16);
            al[mt][3] = *(const uint32_t*)(sm + T_ALx(buf) + ad + 656);
        }
#pragma unroll
        for (int nt = 0; nt < 8; nt++) {
            uint32_t bd = (uint32_t)(wn * 64 + nt * 8 + g) * 80 + kk * 32 + tig * 4;
            uint32_t bh0 = *(const uint32_t*)(Bhs + bd);
            uint32_t bh1 = *(const uint32_t*)(Bhs + bd + 16);
            mma16816(acc[0][nt], ah[0], bh0, bh1);
            mma16816(acc[0][nt], al[0], bh0, bh1);
            mma16816(acc[1][nt], ah[1], bh0, bh1);
            mma16816(acc[1][nt], al[1], bh0, bh1);
            if (br == 1) {
                uint32_t bl0 = *(const uint32_t*)(Bls + bd);
                uint32_t bl1 = *(const uint32_t*)(Bls + bd + 16);
                mma16816(acc[0][nt], ah[0], bl0, bl1);
                mma16816(acc[1][nt], ah[1], bl0, bl1);
            }
        }
    };

    // ---- software pipeline: build(kc+1) overlapped with MMA(kc) ----
    prefetch(0, 0);
    CP_WAIT0();
    __syncthreads();           // prologue + B/P(0) visible
    buildA(0, 0, 0);
    __syncthreads();           // A(0) visible

    for (int kc = 0; kc < 8; kc++) {
        int buf = kc & 1;
        if (kc < 7) prefetch(kc + 1, buf ^ 1);
        mmaBlk(0, buf);
        if (kc < 7) {
            CP_WAIT0();        // P(kc+1)/B(kc+1) landed
            buildA(kc + 1, buf ^ 1, buf ^ 1);
        }
        mmaBlk(1, buf);
        __syncthreads();       // A(kc+1), B(kc+1) ready; A(kc), B(kc) free
    }

    // ---- epilogue: per group, stage M=silu(acc+b2), reduce ----
    float* Ms = (float*)(sm + T_MS);
    for (int gsel = 0; gsel < 2; gsel++) {
        __syncthreads();
        if ((wm >> 1) == gsel) {
#pragma unroll
            for (int mt = 0; mt < 2; mt++)
#pragma unroll
                for (int nt = 0; nt < 8; nt++)
#pragma unroll
                    for (int r = 0; r < 4; r++) {
                        int row = wm * 32 + mt * 16 + g + (r >> 1) * 8;
                        int jr = row - gsel * 64;
                        int col = wn * 64 + nt * 8 + 2 * tig + (r & 1);
                        Ms[jr * 260 + col] = siluf(acc[mt][nt][r] + sb2[col]);
                    }
        }
        __syncthreads();
        // per-row dot with sw3 (rotated, conflict-free)
        {
            int j = tid >> 3, qq = tid & 7;
            const float* Mr = &Ms[j * 260 + qq * 32];
            const float* wr = &sw3[qq * 32];
            float p = 0.f;
#pragma unroll
            for (int n = 0; n < 32; n++) {
                int nn = (n + 4 * qq) & 31;
                p = fmaf(Mr[nn], wr[nn], p);
            }
            p += __shfl_xor_sync(0xffffffffu, p, 1);
            p += __shfl_xor_sync(0xffffffffu, p, 2);
            p += __shfl_xor_sync(0xffffffffu, p, 4);
            if (qq == 0) sa[j] = br ? p : sigmf_(p + attn_b[l]);
        }
        __syncthreads();
        int bi = bi0 + gsel;
        if (br == 0) {
            if (tid < 256) {
                float s = 0.f;
                for (int j2 = 0; j2 < 64; j2++) s = fmaf(sa[j2], Ms[j2 * 260 + tid], s);
                g_em[(size_t)bi * HID + tid] = s;
            }
        } else if (tid < 3) {
            float accx = 0.f;
            for (int j2 = 0; j2 < 64; j2++) {
                int e = gsel * 64 + j2;
                accx = fmaf(sdiff[e * 3 + tid] / (sdv[e] + 1.f), sa[j2], accx);
            }
            g_x[1 - cur][bi * 3 + tid] = (x[bi * 3 + tid] + accx) * node_mask[bi];
        }
    }
}

// ======================= node MLP =======================
__global__ void k_hupd(int l, int cur,
        const float* __restrict__ wh_w1, const float* __restrict__ wh_b1,
        const float* __restrict__ wh_w2, const float* __restrict__ wh_b2,
        const float* __restrict__ node_mask) {
    int r0 = blockIdx.x * 16;
    int tid = threadIdx.x;
    __shared__ float sin_[16][512];
    __shared__ float shid[16][HID];
    const float* h = g_h[cur];
    for (int idx = tid; idx < 16 * 512; idx += 256) {
        int r = idx >> 9, k = idx & 511;
        sin_[r][k] = (k < HID) ? h[(r0 + r) * HID + k] : g_em[(r0 + r) * HID + (k - HID)];
    }
    __syncthreads();
    const float* W1 = wh_w1 + (size_t)l * 512 * HID;
    const float* W2 = wh_w2 + (size_t)l * HID * HID;
    float b1v = wh_b1[l * HID + tid];
    float acc[16];
#pragma unroll
    for (int r = 0; r < 16; r++) acc[r] = 0.f;
#pragma unroll 4
    for (int k = 0; k < 512; k++) {
        float w = W1[k * HID + tid];
#pragma unroll
        for (int r = 0; r < 16; r++) acc[r] = fmaf(sin_[r][k], w, acc[r]);
    }
#pragma unroll
    for (int r = 0; r < 16; r++) shid[r][tid] = siluf(acc[r] + b1v);
    __syncthreads();
    float b2v = wh_b2[l * HID + tid];
#pragma unroll
    for (int r = 0; r < 16; r++) acc[r] = 0.f;
#pragma unroll 4
    for (int k = 0; k < HID; k++) {
        float w = W2[k * HID + tid];
#pragma unroll
        for (int r = 0; r < 16; r++) acc[r] = fmaf(shid[r][k], w, acc[r]);
    }
    float* ho = g_h[1 - cur];
#pragma unroll
    for (int r = 0; r < 16; r++) {
        int row = r0 + r;
        ho[row * HID + tid] = (h[row * HID + tid] + acc[r] + b2v) * node_mask[row];
    }
}

// ======================= final =======================
__global__ void k_final(const float* __restrict__ x_in, const float* __restrict__ node_mask,
                        const float* __restrict__ wout_w, const float* __restrict__ wout_b,
                        float* __restrict__ out, int fin) {
    int b = blockIdx.x, tid = threadIdx.x;
    __shared__ float sxd[NN][3];
    __shared__ float smean[3];
    const float* x = g_x[fin];
    const float* h = g_h[fin];
    if (tid < NN) {
        float m = node_mask[b * NN + tid];
#pragma unroll
        for (int k = 0; k < 3; k++)
            sxd[tid][k] = (x[(b * NN + tid) * 3 + k] - x_in[(b * NN + tid) * 3 + k]) * m;
    }
    __syncthreads();
    if (tid < 3) {
        float s = 0.f, n = 0.f;
        for (int nd = 0; nd < NN; nd++) { s += sxd[nd][tid]; n += node_mask[b * NN + nd]; }
        smean[tid] = s / n;
    }
    __syncthreads();
    if (tid < NN) {
        float m = node_mask[b * NN + tid];
#pragma unroll
        for (int k = 0; k < 3; k++)
            out[(b * NN + tid) * 8 + k] = (sxd[tid][k] - smean[k]) * m;
    }
    for (int p = tid; p < NN * 5; p += 256) {
        int nd = p / 5, c = p % 5;
        float accv = wout_b[c];
        const float* hr = &h[(b * NN + nd) * HID];
        for (int k = 0; k < HID; k++) accv = fmaf(hr[k], wout_w[k * 6 + c], accv);
        out[(b * NN + nd) * 8 + 3 + c] = accv * node_mask[b * NN + nd];
    }
}

// ======================= host launcher =======================
extern "C" void kernel_launch(void* const* d_in, const int* in_sizes, int n_in,
                              void* d_out, int out_size) {
    const float* x_in      = (const float*)d_in[0];
    const float* h_in      = (const float*)d_in[1];
    const float* t         = (const float*)d_in[2];
    const float* node_mask = (const float*)d_in[3];
    const float* edge_mask = (const float*)d_in[4];
    const float* win_w  = (const float*)d_in[6];
    const float* win_b  = (const float*)d_in[7];
    const float* wout_w = (const float*)d_in[8];
    const float* wout_b = (const float*)d_in[9];
    const float* we_w1  = (const float*)d_in[10];
    const float* we_b1  = (const float*)d_in[11];
    const float* we_w2  = (const float*)d_in[12];
    const float* we_b2  = (const float*)d_in[13];
    const float* attn_w = (const float*)d_in[14];
    const float* attn_b = (const float*)d_in[15];
    const float* wh_w1  = (const float*)d_in[16];
    const float* wh_b1  = (const float*)d_in[17];
    const float* wh_w2  = (const float*)d_in[18];
    const float* wh_b2  = (const float*)d_in[19];
    const float* wx_w1  = (const float*)d_in[20];
    const float* wx_b1  = (const float*)d_in[21];
    const float* wx_w2  = (const float*)d_in[22];
    const float* wx_b2  = (const float*)d_in[23];
    const float* wx_w3  = (const float*)d_in[24];
    float* out = (float*)d_out;

    cudaFuncSetAttribute(k_egemm, cudaFuncAttributeMaxDynamicSharedMemorySize, EG_SMEM);

    k_init<<<BB * NN, 256>>>(h_in, t, win_w, win_b, x_in);
    k_din<<<BB * EE / 256, 256>>>(x_in, edge_mask);
    k_wsplit<<<dim3(NL, 2), 256>>>(we_w2, wx_w2);

    for (int l = 0; l < NL; l++) {
        int cur = l & 1;
        k_proj<<<dim3(BB * NN / 16, 4), 256>>>(l, cur, we_w1, wx_w1);
        k_egemm<<<dim3(BB * EE / 128, 2), 512, EG_SMEM>>>(l, cur,
            we_w1, we_b1, we_b2, attn_w, attn_b,
            wx_w1, wx_b1, wx_b2, wx_w3, edge_mask, node_mask);
        k_hupd<<<BB * NN / 16, 256>>>(l, cur, wh_w1, wh_b1, wh_w2, wh_b2, node_mask);
    }
    k_final<<<BB, 256>>>(x_in, node_mask, wout_w, wout_b, out, 1);
}